// round 3
// baseline (speedup 1.0000x reference)
#include <cuda_runtime.h>
#include <cuda_fp16.h>

#define N_NODES 50000
#define N_EDGES 1600000
#define NCLS    48
#define NH2     24            // half2 per row
#define NSTEP   10
#define SCAN_B  1024
#define CHUNK   49            // ceil(50000/1024)

// ---------------- device scratch (static, no runtime allocation) -------------
__device__ float   g_deg[N_NODES];
__device__ int     g_cnt[N_NODES];
__device__ int     g_off[N_NODES + 1];
__device__ int     g_cur[N_NODES];
__device__ int2    g_edge[N_EDGES];                  // (src, weight-as-int)
__device__ __half2 g_hh[2][(size_t)N_NODES * NH2];   // fp16 feature buffers

// ---------------- preprocessing ------------------------------------------------
// degree accumulation + in-degree counting + one-hot init, fused
__global__ void deg_h0_kernel(const int* __restrict__ row, const int* __restrict__ col,
                              const float* __restrict__ attr, const int* __restrict__ target) {
    int e = blockIdx.x * blockDim.x + threadIdx.x;
    if (e < N_EDGES) {
        atomicAdd(&g_deg[row[e]], attr[e]);
        atomicAdd(&g_cnt[col[e]], 1);
    }
    if (e < N_NODES * NH2) {
        int n  = e / NH2;
        int c2 = (e - n * NH2) * 2;
        int t  = target[n];
        g_hh[0][e] = __floats2half2_rn(t == c2 ? 1.0f : 0.0f,
                                       t == c2 + 1 ? 1.0f : 0.0f);
    }
}

// single-block exclusive scan of g_cnt -> g_off / g_cur (3-phase)
__global__ void scan_kernel() {
    __shared__ int sh[SCAN_B];
    int tid = threadIdx.x;
    int base = tid * CHUNK;

    // phase 1: per-thread chunk sum
    int sum = 0;
    #pragma unroll 4
    for (int k = 0; k < CHUNK; k++) {
        int i = base + k;
        if (i < N_NODES) sum += g_cnt[i];
    }
    sh[tid] = sum;
    __syncthreads();

    // phase 2: block inclusive scan of 1024 partials
    for (int d = 1; d < SCAN_B; d <<= 1) {
        int t = (tid >= d) ? sh[tid - d] : 0;
        __syncthreads();
        sh[tid] += t;
        __syncthreads();
    }
    int run = sh[tid] - sum;   // exclusive prefix for this thread's chunk

    // phase 3: sequential exclusive scan within chunk
    #pragma unroll 4
    for (int k = 0; k < CHUNK; k++) {
        int i = base + k;
        if (i < N_NODES) {
            g_off[i] = run;
            g_cur[i] = run;
            run += g_cnt[i];
        }
    }
    if (tid == 0) g_off[N_NODES] = N_EDGES;
}

// bucket edges by destination; precompute row-normalized weight; packed 8B store
__global__ void fill_kernel(const int* __restrict__ row, const int* __restrict__ col,
                            const float* __restrict__ attr) {
    int e = blockIdx.x * blockDim.x + threadIdx.x;
    if (e < N_EDGES) {
        int r = row[e];
        int c = col[e];
        float w = attr[e] / fmaxf(g_deg[r], 1e-12f);
        int p = atomicAdd(&g_cur[c], 1);
        g_edge[p] = make_int2(r, __float_as_int(w));
    }
}

// ---------------- main propagation step: one warp per destination node -------
// lanes 0..23 own classes (2l, 2l+1); unroll 8 with front-batched row loads
__global__ void __launch_bounds__(256)
gather_kernel(const float* __restrict__ Wm, float* __restrict__ out, int s) {
    int gwarp = (blockIdx.x * blockDim.x + threadIdx.x) >> 5;
    int lane  = threadIdx.x & 31;
    if (gwarp >= N_NODES) return;

    const __half2* __restrict__ hin  = g_hh[s & 1];
    __half2*       __restrict__ hout = g_hh[(s & 1) ^ 1];

    int beg = g_off[gwarp];
    int end = g_off[gwarp + 1];
    bool act = (lane < NH2);

    float ax0 = 0.f, ay0 = 0.f, ax1 = 0.f, ay1 = 0.f;
    float ax2 = 0.f, ay2 = 0.f, ax3 = 0.f, ay3 = 0.f;

    int j = beg;
    for (; j + 8 <= end; j += 8) {
        int2 e[8];
        #pragma unroll
        for (int k = 0; k < 8; k++) e[k] = g_edge[j + k];
        if (act) {
            float2 x[8];
            #pragma unroll
            for (int k = 0; k < 8; k++)
                x[k] = __half22float2(hin[(size_t)e[k].x * NH2 + lane]);
            #pragma unroll
            for (int k = 0; k < 8; k++) {
                float w = __int_as_float(e[k].y);
                switch (k & 3) {
                    case 0: ax0 = fmaf(w, x[k].x, ax0); ay0 = fmaf(w, x[k].y, ay0); break;
                    case 1: ax1 = fmaf(w, x[k].x, ax1); ay1 = fmaf(w, x[k].y, ay1); break;
                    case 2: ax2 = fmaf(w, x[k].x, ax2); ay2 = fmaf(w, x[k].y, ay2); break;
                    default: ax3 = fmaf(w, x[k].x, ax3); ay3 = fmaf(w, x[k].y, ay3); break;
                }
            }
        }
    }
    for (; j + 4 <= end; j += 4) {
        int2 e0 = g_edge[j], e1 = g_edge[j + 1], e2 = g_edge[j + 2], e3 = g_edge[j + 3];
        if (act) {
            float2 x0 = __half22float2(hin[(size_t)e0.x * NH2 + lane]);
            float2 x1 = __half22float2(hin[(size_t)e1.x * NH2 + lane]);
            float2 x2 = __half22float2(hin[(size_t)e2.x * NH2 + lane]);
            float2 x3 = __half22float2(hin[(size_t)e3.x * NH2 + lane]);
            float w0 = __int_as_float(e0.y), w1 = __int_as_float(e1.y);
            float w2 = __int_as_float(e2.y), w3 = __int_as_float(e3.y);
            ax0 = fmaf(w0, x0.x, ax0); ay0 = fmaf(w0, x0.y, ay0);
            ax1 = fmaf(w1, x1.x, ax1); ay1 = fmaf(w1, x1.y, ay1);
            ax2 = fmaf(w2, x2.x, ax2); ay2 = fmaf(w2, x2.y, ay2);
            ax3 = fmaf(w3, x3.x, ax3); ay3 = fmaf(w3, x3.y, ay3);
        }
    }
    for (; j < end; j++) {
        int2 e = g_edge[j];
        if (act) {
            float2 x = __half22float2(hin[(size_t)e.x * NH2 + lane]);
            float w = __int_as_float(e.y);
            ax0 = fmaf(w, x.x, ax0); ay0 = fmaf(w, x.y, ay0);
        }
    }

    if (act) {
        float accx = (ax0 + ax1) + (ax2 + ax3);
        float accy = (ay0 + ay1) + (ay2 + ay3);

        hout[(size_t)gwarp * NH2 + lane] = __floats2half2_rn(accx, accy);

        float2 o;
        o.x = accx * Wm[(2 * lane) * NSTEP + s];
        o.y = accy * Wm[(2 * lane + 1) * NSTEP + s];
        float2* op = (float2*)(out + (size_t)gwarp * NCLS) + lane;
        if (s != 0) { float2 p = *op; o.x += p.x; o.y += p.y; }
        *op = o;
    }
}

// ---------------- launch ------------------------------------------------------
extern "C" void kernel_launch(void* const* d_in, const int* in_sizes, int n_in,
                              void* d_out, int out_size) {
    const int*   ei     = (const int*)d_in[0];     // [2, E]
    const int*   row    = ei;
    const int*   col    = ei + N_EDGES;
    const float* attr   = (const float*)d_in[1];   // [E]
    const int*   target = (const int*)d_in[2];     // [N]
    const float* Wm     = (const float*)d_in[3];   // [C, S]
    float*       out    = (float*)d_out;           // [N, C]

    // zero deg/cnt via async memset (graph-capturable, not a kernel launch)
    void* p_deg = nullptr; void* p_cnt = nullptr;
    cudaGetSymbolAddress(&p_deg, g_deg);
    cudaGetSymbolAddress(&p_cnt, g_cnt);
    cudaMemsetAsync(p_deg, 0, N_NODES * sizeof(float));
    cudaMemsetAsync(p_cnt, 0, N_NODES * sizeof(int));

    const int TB = 256;
    int nblk_edges = (N_EDGES + TB - 1) / TB;

    deg_h0_kernel<<<nblk_edges, TB>>>(row, col, attr, target);  // launch 1
    scan_kernel<<<1, SCAN_B>>>();                               // launch 2
    fill_kernel<<<nblk_edges, TB>>>(row, col, attr);            // launch 3

    int nblk_gather = (N_NODES + 7) / 8;   // 8 warps/block, 1 node/warp
    for (int s = 0; s < NSTEP; s++) {
        gather_kernel<<<nblk_gather, TB>>>(Wm, out, s);         // launches 4..13
    }
}

// round 4
// speedup vs baseline: 1.1580x; 1.1580x over previous
#include <cuda_runtime.h>
#include <cuda_fp16.h>

#define N_NODES 50000
#define N_EDGES 1600000
#define NCLS    48
#define NH2     24            // active half2 per row
#define ROWP    32            // padded half2 per row (128B rows)
#define NSTEP   10
#define SCAN_B  1024
#define CHUNK   49            // ceil(50000/1024)

// ---------------- device scratch (static, no runtime allocation) -------------
__device__ float   g_deg[N_NODES];
__device__ int     g_cnt[N_NODES];
__device__ int     g_off[N_NODES + 1];
__device__ int     g_cur[N_NODES];
__device__ __align__(16) int2 g_edge[N_EDGES];       // (src, weight packed half2(w,w))
__device__ __half2 g_hh[2][(size_t)N_NODES * ROWP];  // fp16 feature buffers, 128B rows

static __device__ __forceinline__ __half2 bits2h2(int b) {
    __half2 h; *reinterpret_cast<int*>(&h) = b; return h;
}

// ---------------- preprocessing ------------------------------------------------
// degree accumulation + in-degree counting + one-hot init (padded rows), fused
__global__ void deg_h0_kernel(const int* __restrict__ row, const int* __restrict__ col,
                              const float* __restrict__ attr, const int* __restrict__ target) {
    int e = blockIdx.x * blockDim.x + threadIdx.x;
    if (e < N_EDGES) {
        atomicAdd(&g_deg[row[e]], attr[e]);
        atomicAdd(&g_cnt[col[e]], 1);
    }
    if (e < N_NODES * ROWP) {
        int n  = e >> 5;            // / ROWP
        int c2 = (e & 31) * 2;
        int t  = target[n];
        g_hh[0][e] = __floats2half2_rn(t == c2 ? 1.0f : 0.0f,
                                       t == c2 + 1 ? 1.0f : 0.0f);
    }
}

// single-block exclusive scan of g_cnt -> g_off / g_cur (3-phase)
__global__ void scan_kernel() {
    __shared__ int sh[SCAN_B];
    int tid = threadIdx.x;
    int base = tid * CHUNK;

    int sum = 0;
    #pragma unroll 4
    for (int k = 0; k < CHUNK; k++) {
        int i = base + k;
        if (i < N_NODES) sum += g_cnt[i];
    }
    sh[tid] = sum;
    __syncthreads();
    for (int d = 1; d < SCAN_B; d <<= 1) {
        int t = (tid >= d) ? sh[tid - d] : 0;
        __syncthreads();
        sh[tid] += t;
        __syncthreads();
    }
    int run = sh[tid] - sum;
    #pragma unroll 4
    for (int k = 0; k < CHUNK; k++) {
        int i = base + k;
        if (i < N_NODES) {
            g_off[i] = run;
            g_cur[i] = run;
            run += g_cnt[i];
        }
    }
    if (tid == 0) g_off[N_NODES] = N_EDGES;
}

// bucket edges by destination; weight normalized + packed as half2(w,w)
__global__ void fill_kernel(const int* __restrict__ row, const int* __restrict__ col,
                            const float* __restrict__ attr) {
    int e = blockIdx.x * blockDim.x + threadIdx.x;
    if (e < N_EDGES) {
        int r = row[e];
        int c = col[e];
        float w = attr[e] / fmaxf(g_deg[r], 1e-12f);
        __half2 wh = __floats2half2_rn(w, w);
        int p = atomicAdd(&g_cur[c], 1);
        g_edge[p] = make_int2(r, *reinterpret_cast<int*>(&wh));
    }
}

// ---------------- main propagation step: one warp per destination node -------
// lanes 0..23 own classes (2l, 2l+1); HFMA2 accumulate, promote to fp32 per 8
__global__ void __launch_bounds__(256)
gather_kernel(const float* __restrict__ Wm, float* __restrict__ out, int s) {
    int gwarp = (blockIdx.x * blockDim.x + threadIdx.x) >> 5;
    int lane  = threadIdx.x & 31;
    if (gwarp >= N_NODES) return;

    const __half2* __restrict__ hin  = g_hh[s & 1] + lane;   // lane-offset base
    __half2*       __restrict__ hout = g_hh[(s & 1) ^ 1];

    int beg = g_off[gwarp];
    int end = g_off[gwarp + 1];
    bool act = (lane < NH2);

    float accx = 0.f, accy = 0.f;
    __half2 hacc = __floats2half2_rn(0.f, 0.f);   // peel + remainder accumulator

    int j = beg;
    // peel one edge if beg is odd (align int4 metadata loads)
    if ((j & 1) && j < end) {
        int2 e = g_edge[j];
        if (act) {
            __half2 x = hin[(unsigned)e.x << 5];
            hacc = __hfma2(bits2h2(e.y), x, hacc);
        }
        j++;
    }

    for (; j + 8 <= end; j += 8) {
        int4 m0 = *reinterpret_cast<const int4*>(g_edge + j);
        int4 m1 = *reinterpret_cast<const int4*>(g_edge + j + 2);
        int4 m2 = *reinterpret_cast<const int4*>(g_edge + j + 4);
        int4 m3 = *reinterpret_cast<const int4*>(g_edge + j + 6);
        if (act) {
            __half2 x0 = hin[(unsigned)m0.x << 5];
            __half2 x1 = hin[(unsigned)m0.z << 5];
            __half2 x2 = hin[(unsigned)m1.x << 5];
            __half2 x3 = hin[(unsigned)m1.z << 5];
            __half2 x4 = hin[(unsigned)m2.x << 5];
            __half2 x5 = hin[(unsigned)m2.z << 5];
            __half2 x6 = hin[(unsigned)m3.x << 5];
            __half2 x7 = hin[(unsigned)m3.z << 5];
            __half2 p0 = __hmul2(bits2h2(m0.y), x0);
            __half2 p1 = __hmul2(bits2h2(m0.w), x1);
            p0 = __hfma2(bits2h2(m1.y), x2, p0);
            p1 = __hfma2(bits2h2(m1.w), x3, p1);
            p0 = __hfma2(bits2h2(m2.y), x4, p0);
            p1 = __hfma2(bits2h2(m2.w), x5, p1);
            p0 = __hfma2(bits2h2(m3.y), x6, p0);
            p1 = __hfma2(bits2h2(m3.w), x7, p1);
            float2 f = __half22float2(__hadd2(p0, p1));
            accx += f.x;
            accy += f.y;
        }
    }
    // remainder (<= 7 edges) in fp16 chain
    for (; j < end; j++) {
        int2 e = g_edge[j];
        if (act) {
            __half2 x = hin[(unsigned)e.x << 5];
            hacc = __hfma2(bits2h2(e.y), x, hacc);
        }
    }

    if (act) {
        float2 fr = __half22float2(hacc);
        accx += fr.x;
        accy += fr.y;

        hout[(size_t)gwarp * ROWP + lane] = __floats2half2_rn(accx, accy);

        float2 o;
        o.x = accx * Wm[(2 * lane) * NSTEP + s];
        o.y = accy * Wm[(2 * lane + 1) * NSTEP + s];
        float2* op = (float2*)(out + (size_t)gwarp * NCLS) + lane;
        if (s != 0) { float2 p = *op; o.x += p.x; o.y += p.y; }
        *op = o;
    }
}

// ---------------- launch ------------------------------------------------------
extern "C" void kernel_launch(void* const* d_in, const int* in_sizes, int n_in,
                              void* d_out, int out_size) {
    const int*   ei     = (const int*)d_in[0];     // [2, E]
    const int*   row    = ei;
    const int*   col    = ei + N_EDGES;
    const float* attr   = (const float*)d_in[1];   // [E]
    const int*   target = (const int*)d_in[2];     // [N]
    const float* Wm     = (const float*)d_in[3];   // [C, S]
    float*       out    = (float*)d_out;           // [N, C]

    void* p_deg = nullptr; void* p_cnt = nullptr;
    cudaGetSymbolAddress(&p_deg, g_deg);
    cudaGetSymbolAddress(&p_cnt, g_cnt);
    cudaMemsetAsync(p_deg, 0, N_NODES * sizeof(float));
    cudaMemsetAsync(p_cnt, 0, N_NODES * sizeof(int));

    const int TB = 256;
    int nblk_edges = (N_EDGES + TB - 1) / TB;

    deg_h0_kernel<<<nblk_edges, TB>>>(row, col, attr, target);  // launch 1
    scan_kernel<<<1, SCAN_B>>>();                               // launch 2
    fill_kernel<<<nblk_edges, TB>>>(row, col, attr);            // launch 3

    int nblk_gather = (N_NODES + 7) / 8;   // 8 warps/block, 1 node/warp
    for (int s = 0; s < NSTEP; s++) {
        gather_kernel<<<nblk_gather, TB>>>(Wm, out, s);         // launches 4..13
    }
}